// round 13
// baseline (speedup 1.0000x reference)
#include <cuda_runtime.h>

#define T_STEPS 730
#define N_GRID  10000
#define LENF    15
#define NEARZERO 1e-5f
#define BLK   128           // 4 warps; each warp owns 16 cells, fully independent
#define GPB   64            // grid cells per block
#define CPW   16            // cells per warp
#define CHUNK 7             // timesteps per stage
#define NCHUNKS 105         // ceil(730/7); chunk 104 has 2 live steps

// Shared staging: [buf][step][cell data]; each warp touches only its own slice.
// x padded to 4 floats/cell so (P,Ta,PE) is one LDS.128 per thread.
struct __align__(16) Smem {
    float sx[2][CHUNK][GPB * 4];   // P, Ta, PET, pad
    float sd[2][CHUNK][GPB * 4];   // beta_m0, beta_m1, betaet_m0, betaet_m1
};

__device__ __forceinline__ void cp16(void* dst_smem, const void* src) {
    unsigned d = (unsigned)__cvta_generic_to_shared(dst_smem);
    asm volatile("cp.async.ca.shared.global [%0], [%1], 16;\n" :: "r"(d), "l"(src));
}
__device__ __forceinline__ void cp4(void* dst_smem, const void* src) {
    unsigned d = (unsigned)__cvta_generic_to_shared(dst_smem);
    asm volatile("cp.async.ca.shared.global [%0], [%1], 4;\n" :: "r"(d), "l"(src));
}
__device__ __forceinline__ float lg2a(float x) {
    float r; asm("lg2.approx.f32 %0, %1;" : "=f"(r) : "f"(x)); return r;
}
__device__ __forceinline__ float ex2a(float x) {
    float r; asm("ex2.approx.f32 %0, %1;" : "=f"(r) : "f"(x)); return r;
}

// Per-warp staging: warp w stages CHUNK steps of ITS OWN 16 cells into buf ch&1.
// CLAMP only needed for chunk 104 (reads past t=729).
template<bool CLAMP>
__device__ __forceinline__ void stage(
    Smem& s, int ch, int gb, int w, int lane,
    const float* __restrict__ x_phy, const float* __restrict__ pdy)
{
    const int buf = ch & 1;
    const int t0  = ch * CHUNK;
    // x: 7 steps * 48 floats = 336 scalars -> padded stride-4 slots
    const int limx = T_STEPS * N_GRID * 3 - 1;
    #pragma unroll
    for (int v = 0; v < 11; ++v) {
        const int i = lane + v * 32;
        if (v < 10 || i < CHUNK * 48) {
            const int st = i / 48, r = i % 48;         // lane-invariant across calls
            const int cell = r / 3, comp = r % 3;
            int idx = (t0 + st) * (N_GRID * 3) + gb * 3 + w * 48 + r;
            if (CLAMP) idx = (idx > limx) ? limx : idx;
            cp4(&s.sx[buf][st][w * 64 + cell * 4 + comp], x_phy + idx);
        }
    }
    // d: 7 steps * 16 vecs = 112 16B vectors
    const int limd = T_STEPS * N_GRID * 4 - 4;
    #pragma unroll
    for (int v = 0; v < 4; ++v) {
        const int i = lane + v * 32;
        if (i < CHUNK * 16) {
            const int st = i >> 4, o = i & 15;
            int idx = (t0 + st) * (N_GRID * 4) + gb * 4 + w * 64 + o * 4;
            if (CLAMP) idx = (idx > limd) ? limd : idx;
            cp16(&s.sd[buf][st][w * 64 + o * 4], pdy + idx);
        }
    }
}

// Per-component HBV parameters (hoisted/precombined)
struct Chain {
    float parFC, parK0, parK1, parK2, parPERC, parUZL, parTT,
          parCFMAX, parCWH, parC;
    float invFC, invLPFC, crf, gwcap, cfmaxTT, crfTT;
};

// One HBV step + per-component 15-tap routing (weights pre-scaled by 0.5).
// RP = t mod 14 (compile-time): static ring indexing. Slot in buffer = RP%7.
template<int RP>
__device__ __forceinline__ void step_body(
    const Chain& S, float& snowpack, float& meltwater, float& sm, float& suz,
    float& slz, float& lsm,
    const float (&w)[LENF], float (&qh)[14],
    const float* __restrict__ px, const float* __restrict__ pd0,
    const float* __restrict__ pd1,
    bool store_ok, float* __restrict__ outp)
{
    constexpr int SL = RP % 7;
    const float4 xv = *reinterpret_cast<const float4*>(px + SL * (GPB * 4));
    const float P  = xv.x;
    const float Ta = xv.y;
    const float PE = xv.z;
    const float beta   = pd0[SL * (GPB * 4)] * 5.0f + 1.0f;   // [1,6]
    const float betaet = pd1[SL * (GPB * 4)] * 4.7f + 0.3f;   // [0.3,5]

    // swet from carried lsm = lg2(sm_prev * invFC)
    const float swet = __saturatef(ex2a(beta * lsm));

    // --- snow bucket (delta form: melt and refreeze are mutually exclusive) ---
    const bool wet = (Ta >= S.parTT);
    const float melt0 = fmaxf(fmaf(S.parCFMAX, Ta, -S.cfmaxTT), 0.0f); // 0 when cold
    const float refr0 = fmaxf(fmaf(-S.crf, Ta, S.crfTT), 0.0f);       // 0 when wet
    const float spin  = wet ? snowpack : (snowpack + P);
    const float delta = wet ? fminf(melt0, spin) : (0.0f - fminf(refr0, meltwater));
    const float sp1 = spin - delta;
    const float mw1 = meltwater + delta;
    const float tosoil = fmaxf(fmaf(-S.parCWH, sp1, mw1), 0.0f);
    snowpack = sp1;
    meltwater = mw1 - tosoil;
    const float rain = wet ? P : 0.0f;

    // --- soil bucket ---
    const float rpt = rain + tosoil;
    const float recharge = rpt * swet;                 // off-chain (feeds suz)
    const float sm1 = fmaf(-rpt, swet, sm + rpt);      // == sm + rpt - recharge
    const float sm2 = fminf(sm1, S.parFC);
    const float excess = sm1 - sm2;
    const float efb = __saturatef(sm2 * S.invLPFC);
    const float ef  = ex2a(betaet * lg2a(efb));
    const float sm3 = fmaxf(fmaf(-PE, ef, sm2), NEARZERO);
    const float cslz = S.parC * slz;                   // off-chain
    const float s3  = __saturatef(sm3 * S.invFC);
    const float cap = fminf(fmaf(-cslz, s3, cslz), slz);   // == min(cslz*(1-s3), slz)
    const float sm4 = fmaxf(sm3 + cap, NEARZERO);
    float slz2 = fmaxf(slz - cap, NEARZERO);
    sm = sm4;
    lsm = lg2a(sm4 * S.invFC);          // tail: feeds next step's swet

    // --- groundwater buckets ---
    const float suz1 = suz + (recharge + excess);
    const float suz2 = fmaxf(suz1 - S.parPERC, 0.0f);  // == suz1 - min(suz1, PERC)
    const float perc = suz1 - suz2;
    const float q0 = S.parK0 * fmaxf(suz2 - S.parUZL, 0.0f);
    const float suz3 = suz2 - q0;
    const float q1 = S.parK1 * suz3;
    suz = fmaf(-S.parK1, suz3, suz3);
    const float slzp = slz2 + perc;
    const float slza = fmaxf(slzp - S.gwcap, 0.0f);
    const float q2 = S.parK2 * slza;
    slz = slza - q2;
    const float qt = (q0 + q1) + q2;

    // --- routing: own component, 15 taps (weights pre-scaled by 0.5);
    //     flow = own partial + sibling partial (one shfl).
    float a0 = w[0] * qt;
    float a1 = w[5] * qh[(RP + 14 - 5) % 14];
    float a2 = w[10] * qh[(RP + 14 - 10) % 14];
    #pragma unroll
    for (int k = 1; k <= 4; ++k)  a0 = fmaf(w[k], qh[(RP + 14 - k) % 14], a0);
    #pragma unroll
    for (int k = 6; k <= 9; ++k)  a1 = fmaf(w[k], qh[(RP + 14 - k) % 14], a1);
    #pragma unroll
    for (int k = 11; k <= 14; ++k) a2 = fmaf(w[k], qh[(RP + 14 - k) % 14], a2);
    qh[RP] = qt;
    const float partial = (a0 + a1) + a2;
    const float flow = partial + __shfl_xor_sync(0xffffffffu, partial, 1);

    if (store_ok) outp[SL * N_GRID] = flow;
}

__global__ void __launch_bounds__(BLK, 1) hbv_fused(
    const float* __restrict__ x_phy,   // [T, G, 3]
    const float* __restrict__ ac_all,  // [G]
    const float* __restrict__ pdy,     // [T, G, 2, 2]
    const float* __restrict__ pstat,   // [G, 30]
    float* __restrict__ out)           // [T, G]
{
    __shared__ Smem smem;

    const int gb   = blockIdx.x * GPB;
    const int wrp  = threadIdx.x >> 5;
    const int lane = threadIdx.x & 31;
    const int lg   = threadIdx.x >> 1;
    const int m    = threadIdx.x & 1;
    const int g    = gb + lg;

    // Whole-warp early exit (10000 % 16 == 0; no block barriers exist).
    if (gb + wrp * CPW >= N_GRID) return;
    const bool store_ok = (m == 0);

    // ---------- static params ----------
    const float* ps = pstat + g * 30;
    const float Ac = ac_all[g];
    Chain S;
    S.parFC    = ps[0*2+m]  * 950.0f  + 50.0f;
    S.parK0    = ps[1*2+m]  * 0.85f   + 0.05f;
    S.parK1    = ps[2*2+m]  * 0.49f   + 0.01f;
    S.parK2    = ps[3*2+m]  * 0.199f  + 0.001f;
    const float parLP = ps[4*2+m] * 0.8f + 0.2f;
    S.parPERC  = ps[5*2+m]  * 10.0f;
    S.parUZL   = ps[6*2+m]  * 100.0f;
    S.parTT    = ps[7*2+m]  * 5.0f    - 2.5f;
    S.parCFMAX = ps[8*2+m]  * 9.5f    + 0.5f;
    const float parCFR = ps[9*2+m] * 0.1f;
    S.parCWH   = ps[10*2+m] * 0.2f;
    S.parC     = ps[11*2+m];
    const float parRT = ps[12*2+m] * 20.0f;
    const float parAC = ps[13*2+m] * 2500.0f;
    S.invFC   = 1.0f / S.parFC;
    S.invLPFC = 1.0f / (parLP * S.parFC);
    S.crf     = parCFR * S.parCFMAX;
    S.gwcap   = parRT * fminf(fmaxf(1.0f - Ac / (parAC + NEARZERO), 0.0f), 1.0f);
    S.cfmaxTT = S.parCFMAX * S.parTT;
    S.crfTT   = S.crf * S.parTT;

    // ---------- normalized gamma-UH weights (pre-scaled by 0.5) ----------
    const float a_r  = fmaxf(ps[28] * 2.9f, 0.0f) + 0.1f;
    const float th_r = fmaxf(ps[29] * 6.5f, 0.0f) + 0.5f;
    const float am1  = a_r - 1.0f;
    const float ivtl = 1.4426950408889634f / th_r;
    const float LOG2TK[LENF] = {
        -1.0f,        0.5849625f, 1.3219281f, 1.8073549f, 2.1699250f,
         2.4594316f,  2.7004397f, 2.9068906f, 3.0874628f, 3.2479275f,
         3.3923174f,  3.5235620f, 3.6438562f, 3.7548875f, 3.8579810f };
    float w[LENF];
    float wsum = 0.0f;
    #pragma unroll
    for (int k = 0; k < LENF; ++k) {
        const float tk = (float)k + 0.5f;
        w[k] = ex2a(am1 * LOG2TK[k] - tk * ivtl);
        wsum += w[k];
    }
    const float ivw = 0.5f / wsum;
    #pragma unroll
    for (int k = 0; k < LENF; ++k) w[k] *= ivw;

    // ---------- state ----------
    float snowpack = 1e-3f, meltwater = 1e-3f, sm = 1e-3f, suz = 1e-3f, slz = 1e-3f;
    float lsm = lg2a(1e-3f * S.invFC);
    float qh[14];
    #pragma unroll
    for (int k = 0; k < 14; ++k) qh[k] = 0.0f;

    // shared read base pointers
    const float* px0 = &smem.sx[0][0][lg * 4];
    const float* pda = &smem.sd[0][0][lg * 4 + m];       // beta (own component)
    const float* pdb = &smem.sd[0][0][lg * 4 + 2 + m];   // betaet
    const int xstride = CHUNK * GPB * 4;
    const int dstride = CHUNK * GPB * 4;

    // ---------- per-warp pipeline prologue ----------
    stage<false>(smem, 0, gb, wrp, lane, x_phy, pdy);
    asm volatile("cp.async.commit_group;\n");
    stage<false>(smem, 1, gb, wrp, lane, x_phy, pdy);
    asm volatile("cp.async.commit_group;\n");

    #define STEPS7(B) \
        step_body<B+0>(S, snowpack, meltwater, sm, suz, slz, lsm, w, qh, px, p0, p1, store_ok, outp); \
        step_body<B+1>(S, snowpack, meltwater, sm, suz, slz, lsm, w, qh, px, p0, p1, store_ok, outp); \
        step_body<B+2>(S, snowpack, meltwater, sm, suz, slz, lsm, w, qh, px, p0, p1, store_ok, outp); \
        step_body<B+3>(S, snowpack, meltwater, sm, suz, slz, lsm, w, qh, px, p0, p1, store_ok, outp); \
        step_body<B+4>(S, snowpack, meltwater, sm, suz, slz, lsm, w, qh, px, p0, p1, store_ok, outp); \
        step_body<B+5>(S, snowpack, meltwater, sm, suz, slz, lsm, w, qh, px, p0, p1, store_ok, outp); \
        step_body<B+6>(S, snowpack, meltwater, sm, suz, slz, lsm, w, qh, px, p0, p1, store_ok, outp);

    // ---------- main loop: 51 chunk-pairs (chunks 0..101, t = 0..713) ----------
    for (int p = 0; p < 51; ++p) {
        // chunk 2p (buf 0, ring phase 0..6)
        {
            asm volatile("cp.async.wait_group 1;\n");
            __syncwarp();
            const float* px = px0;
            const float* p0 = pda;
            const float* p1 = pdb;
            float* outp = out + (2 * p) * (CHUNK * N_GRID) + g;
            STEPS7(0)
            stage<false>(smem, 2 * p + 2, gb, wrp, lane, x_phy, pdy);
            asm volatile("cp.async.commit_group;\n");
        }
        // chunk 2p+1 (buf 1, ring phase 7..13)
        {
            asm volatile("cp.async.wait_group 1;\n");
            __syncwarp();
            const float* px = px0 + xstride;
            const float* p0 = pda + dstride;
            const float* p1 = pdb + dstride;
            float* outp = out + (2 * p + 1) * (CHUNK * N_GRID) + g;
            STEPS7(7)
            stage<false>(smem, 2 * p + 3, gb, wrp, lane, x_phy, pdy);
            asm volatile("cp.async.commit_group;\n");
        }
    }

    // ---------- chunk 102 (buf 0, phase 0): stages chunk 104 WITH clamping ----------
    {
        asm volatile("cp.async.wait_group 1;\n");
        __syncwarp();
        const float* px = px0;
        const float* p0 = pda;
        const float* p1 = pdb;
        float* outp = out + 102 * (CHUNK * N_GRID) + g;
        STEPS7(0)
        stage<true>(smem, 104, gb, wrp, lane, x_phy, pdy);
        asm volatile("cp.async.commit_group;\n");
    }
    // ---------- chunk 103 (buf 1, phase 7): nothing left to stage ----------
    {
        asm volatile("cp.async.wait_group 1;\n");
        __syncwarp();
        const float* px = px0 + xstride;
        const float* p0 = pda + dstride;
        const float* p1 = pdb + dstride;
        float* outp = out + 103 * (CHUNK * N_GRID) + g;
        STEPS7(7)
        asm volatile("cp.async.commit_group;\n");   // empty group keeps the count pattern
    }
    // ---------- epilogue: chunk 104 (buf 0, phase 0), live steps 728..729 ----------
    asm volatile("cp.async.wait_group 0;\n");
    __syncwarp();
    {
        const float* px = px0;
        const float* p0 = pda;
        const float* p1 = pdb;
        float* outp = out + 104 * (CHUNK * N_GRID) + g;
        step_body<0>(S, snowpack, meltwater, sm, suz, slz, lsm, w, qh, px, p0, p1, store_ok, outp);
        step_body<1>(S, snowpack, meltwater, sm, suz, slz, lsm, w, qh, px, p0, p1, store_ok, outp);
    }
    #undef STEPS7
}

// ---------------------------------------------------------------------------
extern "C" void kernel_launch(void* const* d_in, const int* in_sizes, int n_in,
                              void* d_out, int out_size)
{
    const float* x_phy = (const float*)d_in[0];   // [730,10000,3]
    const float* ac    = (const float*)d_in[1];   // [10000]
    // d_in[2] = elev_all (unused)
    const float* pdy   = (const float*)d_in[3];   // [730,10000,4]
    const float* pstat = (const float*)d_in[4];   // [10000,30]
    float* out = (float*)d_out;                   // [730,10000,1]

    hbv_fused<<<(2 * N_GRID + BLK - 1) / BLK, BLK>>>(x_phy, ac, pdy, pstat, out);
}

// round 14
// speedup vs baseline: 1.0082x; 1.0082x over previous
#include <cuda_runtime.h>

#define T_STEPS 730
#define N_GRID  10000
#define LENF    15
#define NEARZERO 1e-5f
#define BLK   128           // 4 warps; each warp owns 16 cells, fully independent
#define GPB   64            // grid cells per block
#define CPW   16            // cells per warp
#define CHUNK 14            // timesteps per stage == routing-ring period
#define NCHUNKS 53          // ceil(730/14); chunk 52 has 2 live steps

// Dynamic shared staging (50176 B): sx[2][14][GPB*3], sd[2][14][GPB*4]
#define XSTEP  (GPB * 3)            // 192 floats per step
#define DSTEP  (GPB * 4)            // 256 floats per step
#define XBUF   (CHUNK * XSTEP)      // 2688 floats per buffer
#define DBUF   (CHUNK * DSTEP)      // 3584 floats per buffer
#define SX_OFF 0
#define SD_OFF (2 * XBUF)
#define SMEM_BYTES ((2 * XBUF + 2 * DBUF) * 4)   // 50176

__device__ __forceinline__ void cp16(void* dst_smem, const void* src) {
    unsigned d = (unsigned)__cvta_generic_to_shared(dst_smem);
    asm volatile("cp.async.ca.shared.global [%0], [%1], 16;\n" :: "r"(d), "l"(src));
}
__device__ __forceinline__ float lg2a(float x) {
    float r; asm("lg2.approx.f32 %0, %1;" : "=f"(r) : "f"(x)); return r;
}
__device__ __forceinline__ float ex2a(float x) {
    float r; asm("ex2.approx.f32 %0, %1;" : "=f"(r) : "f"(x)); return r;
}

// Per-warp staging: warp w stages CHUNK steps of ITS OWN 16 cells into buf ch&1.
// CLAMP only needed for the final chunk (reads past t=729).
template<bool CLAMP>
__device__ __forceinline__ void stage(
    float* __restrict__ sx, float* __restrict__ sd, int ch, int gb, int w, int lane,
    const float* __restrict__ x_phy, const float* __restrict__ pdy)
{
    const int buf = ch & 1;
    const int t0  = ch * CHUNK;
    // x: 14 steps * 12 vecs = 168 16B vectors per warp slice
    const int limx = T_STEPS * N_GRID * 3 - 4;
    float* sxb = sx + buf * XBUF;
    #pragma unroll
    for (int v = 0; v < 6; ++v) {
        const int i = lane + v * 32;
        if (v < 5 || i < CHUNK * 12) {
            const int st = i / 12, o = i % 12;
            int idx = (t0 + st) * (N_GRID * 3) + gb * 3 + w * 48 + o * 4;
            if (CLAMP) idx = (idx > limx) ? limx : idx;
            cp16(&sxb[st * XSTEP + w * 48 + o * 4], x_phy + idx);
        }
    }
    // d: 14 steps * 16 vecs = 224 16B vectors (exactly 7 warp-iterations)
    const int limd = T_STEPS * N_GRID * 4 - 4;
    float* sdb = sd + buf * DBUF;
    #pragma unroll
    for (int v = 0; v < 7; ++v) {
        const int i = lane + v * 32;
        const int st = i >> 4, o = i & 15;
        int idx = (t0 + st) * (N_GRID * 4) + gb * 4 + w * 64 + o * 4;
        if (CLAMP) idx = (idx > limd) ? limd : idx;
        cp16(&sdb[st * DSTEP + w * 64 + o * 4], pdy + idx);
    }
}

// Per-component HBV parameters (hoisted/precombined)
struct Chain {
    float parFC, parK0, parK1, parK2, parPERC, parUZL, parTT,
          parCFMAX, parCWH, parC;
    float invFC, invLPFC, crf, gwcap, cfmaxTT, crfTT;
};

// One HBV step + per-component 15-tap routing (weights pre-scaled by 0.5).
// RP = t mod 14 (compile-time) == slot in the 14-step buffer.
template<int RP>
__device__ __forceinline__ void step_body(
    const Chain& S, float& snowpack, float& meltwater, float& sm, float& suz,
    float& slz, float& lsm,
    const float (&w)[LENF], float (&qh)[14],
    const float* __restrict__ px, const float* __restrict__ pd0,
    const float* __restrict__ pd1,
    bool store_ok, float* __restrict__ outp)
{
    const float P  = px[RP * XSTEP + 0];
    const float Ta = px[RP * XSTEP + 1];
    const float PE = px[RP * XSTEP + 2];
    const float beta   = pd0[RP * DSTEP] * 5.0f + 1.0f;   // [1,6]
    const float betaet = pd1[RP * DSTEP] * 4.7f + 0.3f;   // [0.3,5]

    // swet from carried lsm = lg2(sm_prev * invFC)
    const float swet = __saturatef(ex2a(beta * lsm));

    // --- snow bucket (delta form: melt and refreeze are mutually exclusive) ---
    const bool wet = (Ta >= S.parTT);
    const float melt0 = fmaxf(fmaf(S.parCFMAX, Ta, -S.cfmaxTT), 0.0f); // 0 when cold
    const float refr0 = fmaxf(fmaf(-S.crf, Ta, S.crfTT), 0.0f);       // 0 when wet
    const float spin  = wet ? snowpack : (snowpack + P);
    const float delta = wet ? fminf(melt0, spin) : (0.0f - fminf(refr0, meltwater));
    const float sp1 = spin - delta;
    const float mw1 = meltwater + delta;
    const float tosoil = fmaxf(fmaf(-S.parCWH, sp1, mw1), 0.0f);
    snowpack = sp1;
    meltwater = mw1 - tosoil;
    const float rain = wet ? P : 0.0f;

    // --- soil bucket ---
    const float rpt = rain + tosoil;
    const float recharge = rpt * swet;                 // off-chain (feeds suz)
    const float sm1 = fmaf(-rpt, swet, sm + rpt);      // == sm + rpt - recharge
    const float sm2 = fminf(sm1, S.parFC);
    const float excess = sm1 - sm2;
    const float efb = __saturatef(sm2 * S.invLPFC);
    const float ef  = ex2a(betaet * lg2a(efb));
    const float sm3 = fmaxf(fmaf(-PE, ef, sm2), NEARZERO);
    const float cslz = S.parC * slz;                   // off-chain
    const float s3  = __saturatef(sm3 * S.invFC);
    const float cap = fminf(fmaf(-cslz, s3, cslz), slz);   // == min(cslz*(1-s3), slz)
    const float sm4 = fmaxf(sm3 + cap, NEARZERO);
    float slz2 = fmaxf(slz - cap, NEARZERO);
    sm = sm4;
    lsm = lg2a(sm4 * S.invFC);          // tail: feeds next step's swet

    // --- groundwater buckets ---
    const float suz1 = suz + (recharge + excess);
    const float suz2 = fmaxf(suz1 - S.parPERC, 0.0f);  // == suz1 - min(suz1, PERC)
    const float perc = suz1 - suz2;
    const float q0 = S.parK0 * fmaxf(suz2 - S.parUZL, 0.0f);
    const float suz3 = suz2 - q0;
    const float q1 = S.parK1 * suz3;
    suz = fmaf(-S.parK1, suz3, suz3);
    const float slzp = slz2 + perc;
    const float slza = fmaxf(slzp - S.gwcap, 0.0f);
    const float q2 = S.parK2 * slza;
    slz = slza - q2;
    const float qt = (q0 + q1) + q2;

    // --- routing: own component, 15 taps (weights pre-scaled by 0.5);
    //     flow = own partial + sibling partial (one shfl).
    float a0 = w[0] * qt;
    float a1 = w[5] * qh[(RP + 14 - 5) % 14];
    float a2 = w[10] * qh[(RP + 14 - 10) % 14];
    #pragma unroll
    for (int k = 1; k <= 4; ++k)  a0 = fmaf(w[k], qh[(RP + 14 - k) % 14], a0);
    #pragma unroll
    for (int k = 6; k <= 9; ++k)  a1 = fmaf(w[k], qh[(RP + 14 - k) % 14], a1);
    #pragma unroll
    for (int k = 11; k <= 14; ++k) a2 = fmaf(w[k], qh[(RP + 14 - k) % 14], a2);
    qh[RP] = qt;
    const float partial = (a0 + a1) + a2;
    const float flow = partial + __shfl_xor_sync(0xffffffffu, partial, 1);

    if (store_ok) outp[RP * N_GRID] = flow;
}

__global__ void __launch_bounds__(BLK, 1) hbv_fused(
    const float* __restrict__ x_phy,   // [T, G, 3]
    const float* __restrict__ ac_all,  // [G]
    const float* __restrict__ pdy,     // [T, G, 2, 2]
    const float* __restrict__ pstat,   // [G, 30]
    float* __restrict__ out)           // [T, G]
{
    extern __shared__ float dsm[];
    float* sx = dsm + SX_OFF;
    float* sd = dsm + SD_OFF;

    const int gb   = blockIdx.x * GPB;
    const int wrp  = threadIdx.x >> 5;
    const int lane = threadIdx.x & 31;
    const int lg   = threadIdx.x >> 1;
    const int m    = threadIdx.x & 1;
    const int g    = gb + lg;

    // Whole-warp early exit (10000 % 16 == 0; no block barriers exist).
    if (gb + wrp * CPW >= N_GRID) return;
    const bool store_ok = (m == 0);

    // ---------- static params ----------
    const float* ps = pstat + g * 30;
    const float Ac = ac_all[g];
    Chain S;
    S.parFC    = ps[0*2+m]  * 950.0f  + 50.0f;
    S.parK0    = ps[1*2+m]  * 0.85f   + 0.05f;
    S.parK1    = ps[2*2+m]  * 0.49f   + 0.01f;
    S.parK2    = ps[3*2+m]  * 0.199f  + 0.001f;
    const float parLP = ps[4*2+m] * 0.8f + 0.2f;
    S.parPERC  = ps[5*2+m]  * 10.0f;
    S.parUZL   = ps[6*2+m]  * 100.0f;
    S.parTT    = ps[7*2+m]  * 5.0f    - 2.5f;
    S.parCFMAX = ps[8*2+m]  * 9.5f    + 0.5f;
    const float parCFR = ps[9*2+m] * 0.1f;
    S.parCWH   = ps[10*2+m] * 0.2f;
    S.parC     = ps[11*2+m];
    const float parRT = ps[12*2+m] * 20.0f;
    const float parAC = ps[13*2+m] * 2500.0f;
    S.invFC   = 1.0f / S.parFC;
    S.invLPFC = 1.0f / (parLP * S.parFC);
    S.crf     = parCFR * S.parCFMAX;
    S.gwcap   = parRT * fminf(fmaxf(1.0f - Ac / (parAC + NEARZERO), 0.0f), 1.0f);
    S.cfmaxTT = S.parCFMAX * S.parTT;
    S.crfTT   = S.crf * S.parTT;

    // ---------- normalized gamma-UH weights (pre-scaled by 0.5) ----------
    const float a_r  = fmaxf(ps[28] * 2.9f, 0.0f) + 0.1f;
    const float th_r = fmaxf(ps[29] * 6.5f, 0.0f) + 0.5f;
    const float am1  = a_r - 1.0f;
    const float ivtl = 1.4426950408889634f / th_r;
    const float LOG2TK[LENF] = {
        -1.0f,        0.5849625f, 1.3219281f, 1.8073549f, 2.1699250f,
         2.4594316f,  2.7004397f, 2.9068906f, 3.0874628f, 3.2479275f,
         3.3923174f,  3.5235620f, 3.6438562f, 3.7548875f, 3.8579810f };
    float w[LENF];
    float wsum = 0.0f;
    #pragma unroll
    for (int k = 0; k < LENF; ++k) {
        const float tk = (float)k + 0.5f;
        w[k] = ex2a(am1 * LOG2TK[k] - tk * ivtl);
        wsum += w[k];
    }
    const float ivw = 0.5f / wsum;
    #pragma unroll
    for (int k = 0; k < LENF; ++k) w[k] *= ivw;

    // ---------- state ----------
    float snowpack = 1e-3f, meltwater = 1e-3f, sm = 1e-3f, suz = 1e-3f, slz = 1e-3f;
    float lsm = lg2a(1e-3f * S.invFC);
    float qh[14];
    #pragma unroll
    for (int k = 0; k < 14; ++k) qh[k] = 0.0f;

    // shared read base pointers
    const float* px0 = sx + lg * 3;
    const float* pda = sd + lg * 4 + m;       // beta (own component)
    const float* pdb = sd + lg * 4 + 2 + m;   // betaet

    // ---------- per-warp pipeline prologue ----------
    stage<false>(sx, sd, 0, gb, wrp, lane, x_phy, pdy);
    asm volatile("cp.async.commit_group;\n");
    stage<false>(sx, sd, 1, gb, wrp, lane, x_phy, pdy);
    asm volatile("cp.async.commit_group;\n");

    #define STEPS14 \
        step_body< 0>(S, snowpack, meltwater, sm, suz, slz, lsm, w, qh, px, p0, p1, store_ok, outp); \
        step_body< 1>(S, snowpack, meltwater, sm, suz, slz, lsm, w, qh, px, p0, p1, store_ok, outp); \
        step_body< 2>(S, snowpack, meltwater, sm, suz, slz, lsm, w, qh, px, p0, p1, store_ok, outp); \
        step_body< 3>(S, snowpack, meltwater, sm, suz, slz, lsm, w, qh, px, p0, p1, store_ok, outp); \
        step_body< 4>(S, snowpack, meltwater, sm, suz, slz, lsm, w, qh, px, p0, p1, store_ok, outp); \
        step_body< 5>(S, snowpack, meltwater, sm, suz, slz, lsm, w, qh, px, p0, p1, store_ok, outp); \
        step_body< 6>(S, snowpack, meltwater, sm, suz, slz, lsm, w, qh, px, p0, p1, store_ok, outp); \
        step_body< 7>(S, snowpack, meltwater, sm, suz, slz, lsm, w, qh, px, p0, p1, store_ok, outp); \
        step_body< 8>(S, snowpack, meltwater, sm, suz, slz, lsm, w, qh, px, p0, p1, store_ok, outp); \
        step_body< 9>(S, snowpack, meltwater, sm, suz, slz, lsm, w, qh, px, p0, p1, store_ok, outp); \
        step_body<10>(S, snowpack, meltwater, sm, suz, slz, lsm, w, qh, px, p0, p1, store_ok, outp); \
        step_body<11>(S, snowpack, meltwater, sm, suz, slz, lsm, w, qh, px, p0, p1, store_ok, outp); \
        step_body<12>(S, snowpack, meltwater, sm, suz, slz, lsm, w, qh, px, p0, p1, store_ok, outp); \
        step_body<13>(S, snowpack, meltwater, sm, suz, slz, lsm, w, qh, px, p0, p1, store_ok, outp);

    // ---------- main loop: 52 full chunks (t = 0..727) ----------
    for (int ch = 0; ch < NCHUNKS - 1; ++ch) {
        asm volatile("cp.async.wait_group 1;\n");
        __syncwarp();
        const int buf = ch & 1;
        const float* px = px0 + buf * XBUF;
        const float* p0 = pda + buf * DBUF;
        const float* p1 = pdb + buf * DBUF;
        float* outp = out + ch * (CHUNK * N_GRID) + g;
        STEPS14
        if (ch + 2 < NCHUNKS - 1)
            stage<false>(sx, sd, ch + 2, gb, wrp, lane, x_phy, pdy);
        else if (ch + 2 == NCHUNKS - 1)
            stage<true>(sx, sd, ch + 2, gb, wrp, lane, x_phy, pdy);
        asm volatile("cp.async.commit_group;\n");
    }

    // ---------- epilogue: chunk 52 (buf 0), live steps 728..729 (RP 0,1) ----------
    asm volatile("cp.async.wait_group 0;\n");
    __syncwarp();
    {
        const float* px = px0;
        const float* p0 = pda;
        const float* p1 = pdb;
        float* outp = out + (NCHUNKS - 1) * (CHUNK * N_GRID) + g;
        step_body<0>(S, snowpack, meltwater, sm, suz, slz, lsm, w, qh, px, p0, p1, store_ok, outp);
        step_body<1>(S, snowpack, meltwater, sm, suz, slz, lsm, w, qh, px, p0, p1, store_ok, outp);
    }
    #undef STEPS14
}

// ---------------------------------------------------------------------------
extern "C" void kernel_launch(void* const* d_in, const int* in_sizes, int n_in,
                              void* d_out, int out_size)
{
    const float* x_phy = (const float*)d_in[0];   // [730,10000,3]
    const float* ac    = (const float*)d_in[1];   // [10000]
    // d_in[2] = elev_all (unused)
    const float* pdy   = (const float*)d_in[3];   // [730,10000,4]
    const float* pstat = (const float*)d_in[4];   // [10000,30]
    float* out = (float*)d_out;                   // [730,10000,1]

    cudaFuncSetAttribute(hbv_fused,
                         cudaFuncAttributeMaxDynamicSharedMemorySize, SMEM_BYTES);
    hbv_fused<<<(2 * N_GRID + BLK - 1) / BLK, BLK, SMEM_BYTES>>>(x_phy, ac, pdy, pstat, out);
}

// round 15
// speedup vs baseline: 1.0390x; 1.0306x over previous
#include <cuda_runtime.h>

#define T_STEPS 730
#define N_GRID  10000
#define LENF    15
#define NEARZERO 1e-5f
#define BLK   128           // 4 warps; each warp owns 16 cells, fully independent
#define GPB   64            // grid cells per block
#define CPW   16            // cells per warp
#define CHUNK 14            // timesteps per stage; routing split uses period-7 rings
#define NCHUNKS 53          // ceil(730/14); chunk 52 has 2 live steps

// Dynamic shared staging (50176 B): sx[2][14][GPB*3], sd[2][14][GPB*4]
#define XSTEP  (GPB * 3)            // 192 floats per step
#define DSTEP  (GPB * 4)            // 256 floats per step
#define XBUF   (CHUNK * XSTEP)      // 2688 floats per buffer
#define DBUF   (CHUNK * DSTEP)      // 3584 floats per buffer
#define SX_OFF 0
#define SD_OFF (2 * XBUF)
#define SMEM_BYTES ((2 * XBUF + 2 * DBUF) * 4)   // 50176

__device__ __forceinline__ void cp16(void* dst_smem, const void* src) {
    unsigned d = (unsigned)__cvta_generic_to_shared(dst_smem);
    asm volatile("cp.async.ca.shared.global [%0], [%1], 16;\n" :: "r"(d), "l"(src));
}
__device__ __forceinline__ float lg2a(float x) {
    float r; asm("lg2.approx.f32 %0, %1;" : "=f"(r) : "f"(x)); return r;
}
__device__ __forceinline__ float ex2a(float x) {
    float r; asm("ex2.approx.f32 %0, %1;" : "=f"(r) : "f"(x)); return r;
}

// Per-warp staging: warp w stages CHUNK steps of ITS OWN 16 cells into buf ch&1.
// CLAMP only needed for the final chunk (reads past t=729).
template<bool CLAMP>
__device__ __forceinline__ void stage(
    float* __restrict__ sx, float* __restrict__ sd, int ch, int gb, int w, int lane,
    const float* __restrict__ x_phy, const float* __restrict__ pdy)
{
    const int buf = ch & 1;
    const int t0  = ch * CHUNK;
    // x: 14 steps * 12 vecs = 168 16B vectors per warp slice
    const int limx = T_STEPS * N_GRID * 3 - 4;
    float* sxb = sx + buf * XBUF;
    #pragma unroll
    for (int v = 0; v < 6; ++v) {
        const int i = lane + v * 32;
        if (v < 5 || i < CHUNK * 12) {
            const int st = i / 12, o = i % 12;
            int idx = (t0 + st) * (N_GRID * 3) + gb * 3 + w * 48 + o * 4;
            if (CLAMP) idx = (idx > limx) ? limx : idx;
            cp16(&sxb[st * XSTEP + w * 48 + o * 4], x_phy + idx);
        }
    }
    // d: 14 steps * 16 vecs = 224 16B vectors (exactly 7 warp-iterations)
    const int limd = T_STEPS * N_GRID * 4 - 4;
    float* sdb = sd + buf * DBUF;
    #pragma unroll
    for (int v = 0; v < 7; ++v) {
        const int i = lane + v * 32;
        const int st = i >> 4, o = i & 15;
        int idx = (t0 + st) * (N_GRID * 4) + gb * 4 + w * 64 + o * 4;
        if (CLAMP) idx = (idx > limd) ? limd : idx;
        cp16(&sdb[st * DSTEP + w * 64 + o * 4], pdy + idx);
    }
}

// Per-component HBV parameters (hoisted/precombined)
struct Chain {
    float parFC, parK0, parK1, parK2, parPERC, parUZL, parTT,
          parCFMAX, parCWH, parC;
    float invFC, invLPFC, crf, gwcap, cfmaxTT, crfTT;
};

// One HBV step + SPLIT 15-tap gamma-UH routing on the component mean:
// thread m0 handles taps 0..7 (7-deep ring of qsum), m1 handles taps 8..14
// (7-deep ring fed by m0's evicted q[t-7] via shfl). Ring slot = RP%7 (static).
// Mean (x0.5) folded into the weights.
template<int RP>
__device__ __forceinline__ void step_body(
    const Chain& S, float& snowpack, float& meltwater, float& sm, float& suz,
    float& slz, float& lsm,
    const float w0eff, const float (&wv)[7], float (&rq)[7], int m,
    const float* __restrict__ px, const float* __restrict__ pd0,
    const float* __restrict__ pd1,
    bool store_ok, float* __restrict__ outp)
{
    constexpr int SL7 = RP % 7;
    const float P  = px[RP * XSTEP + 0];
    const float Ta = px[RP * XSTEP + 1];
    const float PE = px[RP * XSTEP + 2];
    const float beta   = pd0[RP * DSTEP] * 5.0f + 1.0f;   // [1,6]
    const float betaet = pd1[RP * DSTEP] * 4.7f + 0.3f;   // [0.3,5]

    // swet from carried lsm = lg2(sm_prev * invFC)
    const float swet = __saturatef(ex2a(beta * lsm));

    // --- snow bucket (delta form: melt and refreeze are mutually exclusive) ---
    const bool wet = (Ta >= S.parTT);
    const float melt0 = fmaxf(fmaf(S.parCFMAX, Ta, -S.cfmaxTT), 0.0f); // 0 when cold
    const float refr0 = fmaxf(fmaf(-S.crf, Ta, S.crfTT), 0.0f);       // 0 when wet
    const float spin  = wet ? snowpack : (snowpack + P);
    const float delta = wet ? fminf(melt0, spin) : (0.0f - fminf(refr0, meltwater));
    const float sp1 = spin - delta;
    const float mw1 = meltwater + delta;
    const float tosoil = fmaxf(fmaf(-S.parCWH, sp1, mw1), 0.0f);
    snowpack = sp1;
    meltwater = mw1 - tosoil;
    const float rain = wet ? P : 0.0f;

    // --- soil bucket ---
    const float rpt = rain + tosoil;
    const float recharge = rpt * swet;                 // off-chain (feeds suz)
    const float sm1 = fmaf(-rpt, swet, sm + rpt);      // == sm + rpt - recharge
    const float sm2 = fminf(sm1, S.parFC);
    const float excess = sm1 - sm2;
    const float efb = __saturatef(sm2 * S.invLPFC);
    const float ef  = ex2a(betaet * lg2a(efb));
    const float sm3 = fmaxf(fmaf(-PE, ef, sm2), NEARZERO);
    const float cslz = S.parC * slz;                   // off-chain
    const float s3  = __saturatef(sm3 * S.invFC);
    const float cap = fminf(fmaf(-cslz, s3, cslz), slz);   // == min(cslz*(1-s3), slz)
    const float sm4 = fmaxf(sm3 + cap, NEARZERO);
    float slz2 = fmaxf(slz - cap, NEARZERO);
    sm = sm4;
    lsm = lg2a(sm4 * S.invFC);          // tail: feeds next step's swet

    // --- groundwater buckets ---
    const float suz1 = suz + (recharge + excess);
    const float suz2 = fmaxf(suz1 - S.parPERC, 0.0f);  // == suz1 - min(suz1, PERC)
    const float perc = suz1 - suz2;
    const float q0 = S.parK0 * fmaxf(suz2 - S.parUZL, 0.0f);
    const float suz3 = suz2 - q0;
    const float q1 = S.parK1 * suz3;
    suz = fmaf(-S.parK1, suz3, suz3);
    const float slzp = slz2 + perc;
    const float slza = fmaxf(slzp - S.gwcap, 0.0f);
    const float q2 = S.parK2 * slza;
    slz = slza - q2;
    const float qt = (q0 + q1) + q2;

    // --- split routing ---
    // qsum = component sum (mean folded into weights).
    const float qsum = qt + __shfl_xor_sync(0xffffffffu, qt, 1);
    const float evict = rq[SL7];                                    // m0: q[t-7]; m1: q[t-14]
    const float incoming = __shfl_xor_sync(0xffffffffu, evict, 1);  // m1 receives m0's q[t-7]
    float a = w0eff * qsum;                                         // tap 0 (m0 only)
    #pragma unroll
    for (int j = 1; j <= 7; ++j)
        a = fmaf(wv[j - 1], rq[(SL7 + 7 - j) % 7], a);              // taps j / 7+j
    rq[SL7] = m ? incoming : qsum;
    const float flow = a + __shfl_xor_sync(0xffffffffu, a, 1);

    if (store_ok) outp[RP * N_GRID] = flow;
}

__global__ void __launch_bounds__(BLK, 1) hbv_fused(
    const float* __restrict__ x_phy,   // [T, G, 3]
    const float* __restrict__ ac_all,  // [G]
    const float* __restrict__ pdy,     // [T, G, 2, 2]
    const float* __restrict__ pstat,   // [G, 30]
    float* __restrict__ out)           // [T, G]
{
    extern __shared__ float dsm[];
    float* sx = dsm + SX_OFF;
    float* sd = dsm + SD_OFF;

    const int gb   = blockIdx.x * GPB;
    const int wrp  = threadIdx.x >> 5;
    const int lane = threadIdx.x & 31;
    const int lg   = threadIdx.x >> 1;
    const int m    = threadIdx.x & 1;
    const int g    = gb + lg;

    // Whole-warp early exit (10000 % 16 == 0; no block barriers exist).
    if (gb + wrp * CPW >= N_GRID) return;
    const bool store_ok = (m == 0);

    // ---------- static params ----------
    const float* ps = pstat + g * 30;
    const float Ac = ac_all[g];
    Chain S;
    S.parFC    = ps[0*2+m]  * 950.0f  + 50.0f;
    S.parK0    = ps[1*2+m]  * 0.85f   + 0.05f;
    S.parK1    = ps[2*2+m]  * 0.49f   + 0.01f;
    S.parK2    = ps[3*2+m]  * 0.199f  + 0.001f;
    const float parLP = ps[4*2+m] * 0.8f + 0.2f;
    S.parPERC  = ps[5*2+m]  * 10.0f;
    S.parUZL   = ps[6*2+m]  * 100.0f;
    S.parTT    = ps[7*2+m]  * 5.0f    - 2.5f;
    S.parCFMAX = ps[8*2+m]  * 9.5f    + 0.5f;
    const float parCFR = ps[9*2+m] * 0.1f;
    S.parCWH   = ps[10*2+m] * 0.2f;
    S.parC     = ps[11*2+m];
    const float parRT = ps[12*2+m] * 20.0f;
    const float parAC = ps[13*2+m] * 2500.0f;
    S.invFC   = 1.0f / S.parFC;
    S.invLPFC = 1.0f / (parLP * S.parFC);
    S.crf     = parCFR * S.parCFMAX;
    S.gwcap   = parRT * fminf(fmaxf(1.0f - Ac / (parAC + NEARZERO), 0.0f), 1.0f);
    S.cfmaxTT = S.parCFMAX * S.parTT;
    S.crfTT   = S.crf * S.parTT;

    // ---------- normalized gamma-UH weights, split across the thread pair ----------
    // w[k] ∝ ex2(am1·log2 t_k − t_k·(log2e/θ)); mean (x0.5) folded into ivw.
    const float a_r  = fmaxf(ps[28] * 2.9f, 0.0f) + 0.1f;
    const float th_r = fmaxf(ps[29] * 6.5f, 0.0f) + 0.5f;
    const float am1  = a_r - 1.0f;
    const float ivtl = 1.4426950408889634f / th_r;
    const float LOG2TK[LENF] = {
        -1.0f,        0.5849625f, 1.3219281f, 1.8073549f, 2.1699250f,
         2.4594316f,  2.7004397f, 2.9068906f, 3.0874628f, 3.2479275f,
         3.3923174f,  3.5235620f, 3.6438562f, 3.7548875f, 3.8579810f };
    float wfull[LENF];
    float wsum = 0.0f;
    #pragma unroll
    for (int k = 0; k < LENF; ++k) {
        const float tk = (float)k + 0.5f;
        wfull[k] = ex2a(am1 * LOG2TK[k] - tk * ivtl);
        wsum += wfull[k];
    }
    const float ivw = 0.5f / wsum;
    const float w0eff = m ? 0.0f : wfull[0] * ivw;   // tap 0 lives on m0
    float wv[7];
    #pragma unroll
    for (int j = 1; j <= 7; ++j)
        wv[j - 1] = wfull[m ? (7 + j) : j] * ivw;    // m0: taps 1..7; m1: taps 8..14

    // ---------- state ----------
    float snowpack = 1e-3f, meltwater = 1e-3f, sm = 1e-3f, suz = 1e-3f, slz = 1e-3f;
    float lsm = lg2a(1e-3f * S.invFC);
    float rq[7];
    #pragma unroll
    for (int k = 0; k < 7; ++k) rq[k] = 0.0f;

    // shared read base pointers
    const float* px0 = sx + lg * 3;
    const float* pda = sd + lg * 4 + m;       // beta (own component)
    const float* pdb = sd + lg * 4 + 2 + m;   // betaet

    // ---------- per-warp pipeline prologue ----------
    stage<false>(sx, sd, 0, gb, wrp, lane, x_phy, pdy);
    asm volatile("cp.async.commit_group;\n");
    stage<false>(sx, sd, 1, gb, wrp, lane, x_phy, pdy);
    asm volatile("cp.async.commit_group;\n");

    #define STEPS14 \
        step_body< 0>(S, snowpack, meltwater, sm, suz, slz, lsm, w0eff, wv, rq, m, px, p0, p1, store_ok, outp); \
        step_body< 1>(S, snowpack, meltwater, sm, suz, slz, lsm, w0eff, wv, rq, m, px, p0, p1, store_ok, outp); \
        step_body< 2>(S, snowpack, meltwater, sm, suz, slz, lsm, w0eff, wv, rq, m, px, p0, p1, store_ok, outp); \
        step_body< 3>(S, snowpack, meltwater, sm, suz, slz, lsm, w0eff, wv, rq, m, px, p0, p1, store_ok, outp); \
        step_body< 4>(S, snowpack, meltwater, sm, suz, slz, lsm, w0eff, wv, rq, m, px, p0, p1, store_ok, outp); \
        step_body< 5>(S, snowpack, meltwater, sm, suz, slz, lsm, w0eff, wv, rq, m, px, p0, p1, store_ok, outp); \
        step_body< 6>(S, snowpack, meltwater, sm, suz, slz, lsm, w0eff, wv, rq, m, px, p0, p1, store_ok, outp); \
        step_body< 7>(S, snowpack, meltwater, sm, suz, slz, lsm, w0eff, wv, rq, m, px, p0, p1, store_ok, outp); \
        step_body< 8>(S, snowpack, meltwater, sm, suz, slz, lsm, w0eff, wv, rq, m, px, p0, p1, store_ok, outp); \
        step_body< 9>(S, snowpack, meltwater, sm, suz, slz, lsm, w0eff, wv, rq, m, px, p0, p1, store_ok, outp); \
        step_body<10>(S, snowpack, meltwater, sm, suz, slz, lsm, w0eff, wv, rq, m, px, p0, p1, store_ok, outp); \
        step_body<11>(S, snowpack, meltwater, sm, suz, slz, lsm, w0eff, wv, rq, m, px, p0, p1, store_ok, outp); \
        step_body<12>(S, snowpack, meltwater, sm, suz, slz, lsm, w0eff, wv, rq, m, px, p0, p1, store_ok, outp); \
        step_body<13>(S, snowpack, meltwater, sm, suz, slz, lsm, w0eff, wv, rq, m, px, p0, p1, store_ok, outp);

    // ---------- main loop: 52 full chunks (t = 0..727) ----------
    for (int ch = 0; ch < NCHUNKS - 1; ++ch) {
        asm volatile("cp.async.wait_group 1;\n");
        __syncwarp();
        const int buf = ch & 1;
        const float* px = px0 + buf * XBUF;
        const float* p0 = pda + buf * DBUF;
        const float* p1 = pdb + buf * DBUF;
        float* outp = out + ch * (CHUNK * N_GRID) + g;
        STEPS14
        if (ch + 2 < NCHUNKS - 1)
            stage<false>(sx, sd, ch + 2, gb, wrp, lane, x_phy, pdy);
        else if (ch + 2 == NCHUNKS - 1)
            stage<true>(sx, sd, ch + 2, gb, wrp, lane, x_phy, pdy);
        asm volatile("cp.async.commit_group;\n");
    }

    // ---------- epilogue: chunk 52 (buf 0), live steps 728..729 (RP 0,1) ----------
    asm volatile("cp.async.wait_group 0;\n");
    __syncwarp();
    {
        const float* px = px0;
        const float* p0 = pda;
        const float* p1 = pdb;
        float* outp = out + (NCHUNKS - 1) * (CHUNK * N_GRID) + g;
        step_body<0>(S, snowpack, meltwater, sm, suz, slz, lsm, w0eff, wv, rq, m, px, p0, p1, store_ok, outp);
        step_body<1>(S, snowpack, meltwater, sm, suz, slz, lsm, w0eff, wv, rq, m, px, p0, p1, store_ok, outp);
    }
    #undef STEPS14
}

// ---------------------------------------------------------------------------
extern "C" void kernel_launch(void* const* d_in, const int* in_sizes, int n_in,
                              void* d_out, int out_size)
{
    const float* x_phy = (const float*)d_in[0];   // [730,10000,3]
    const float* ac    = (const float*)d_in[1];   // [10000]
    // d_in[2] = elev_all (unused)
    const float* pdy   = (const float*)d_in[3];   // [730,10000,4]
    const float* pstat = (const float*)d_in[4];   // [10000,30]
    float* out = (float*)d_out;                   // [730,10000,1]

    cudaFuncSetAttribute(hbv_fused,
                         cudaFuncAttributeMaxDynamicSharedMemorySize, SMEM_BYTES);
    hbv_fused<<<(2 * N_GRID + BLK - 1) / BLK, BLK, SMEM_BYTES>>>(x_phy, ac, pdy, pstat, out);
}